// round 6
// baseline (speedup 1.0000x reference)
#include <cuda_runtime.h>
#include <cuda_bf16.h>

#define N_NODES 100000
#define N_EDGES 1000000
#define D_FEAT  64
#define MAXD    96

// Adjacency buckets. g_cnt zero-initialized at load; k_gin resets each node's
// counter after consuming it, so every graph replay sees identical state.
__device__ int g_cnt[N_NODES];
__device__ int g_adj[(size_t)N_NODES * MAXD];

// ---------------------------------------------------------------------------
// Fill: bucket both directions of each edge. int4-vectorized edge reads.
// ---------------------------------------------------------------------------
__global__ void k_fill(const int4* __restrict__ ra4, const int4* __restrict__ rb4) {
    int i = blockIdx.x * blockDim.x + threadIdx.x;
    if (i >= N_EDGES / 4) return;
    int4 a4 = __ldg(&ra4[i]);
    int4 b4 = __ldg(&rb4[i]);
    int as[4] = {a4.x, a4.y, a4.z, a4.w};
    int bs[4] = {b4.x, b4.y, b4.z, b4.w};
    #pragma unroll
    for (int j = 0; j < 4; j++) {
        int a = as[j], b = bs[j];
        int pa = atomicAdd(&g_cnt[a], 1);
        if (pa < MAXD) g_adj[(size_t)a * MAXD + pa] = b;
        int pb = atomicAdd(&g_cnt[b], 1);
        if (pb < MAXD) g_adj[(size_t)b * MAXD + pb] = a;
    }
}

// ---------------------------------------------------------------------------
// Fused warp-gather + register-fragment TF32 MLP:
//   out = relu(relu((X[v] + sum_nbr X[u]) @ Wh + bh) @ Wo + bo)
// 256 threads = 8 warps; warp w owns local rows [16w, 16w+16):
//   gather: whole warp accumulates one node row at a time (lane = float2 of
//           the row; LDG.64 fully coalesced; degree loop warp-uniform).
//   mma:    k-permuted A fragments from own Ts stripe (syncwarp only);
//           layer-1 accumulators ARE the layer-2 A fragment (W2 rows permuted);
//           weights packed in fragment order -> one LDS.64 per (s,nt).
// ---------------------------------------------------------------------------
#define TS 68
#define GIN_SMEM ((2 * 4096 + 128 * TS) * 4)   // Wp + Ts = 67584 bytes

__device__ __forceinline__ unsigned f2tf32(float f) {
    unsigned u;
    asm("cvt.rna.tf32.f32 %0, %1;" : "=r"(u) : "f"(f));
    return u;
}

__device__ __forceinline__ void mma_tf32(float* d, unsigned a0, unsigned a1,
                                         unsigned a2, unsigned a3,
                                         unsigned b0, unsigned b1) {
    asm volatile(
        "mma.sync.aligned.m16n8k8.row.col.f32.tf32.tf32.f32 "
        "{%0,%1,%2,%3}, {%4,%5,%6,%7}, {%8,%9}, {%0,%1,%2,%3};\n"
        : "+f"(d[0]), "+f"(d[1]), "+f"(d[2]), "+f"(d[3])
        : "r"(a0), "r"(a1), "r"(a2), "r"(a3), "r"(b0), "r"(b1));
}

__global__ __launch_bounds__(256)
void k_gin(const float2* __restrict__ X2,
           const float* __restrict__ Wh_g, const float* __restrict__ bh,
           const float* __restrict__ Wo_g, const float* __restrict__ bo,
           float* __restrict__ out) {
    extern __shared__ unsigned sm[];
    unsigned* Wp = sm;              // [2][4096] packed weight fragments
    unsigned* Ts = sm + 8192;       // [128][TS] aggregated tile (tf32)

    const int tid  = threadIdx.x;
    const int lane = tid & 31;
    const int warp = tid >> 5;
    const int g    = lane >> 2;      // 0..7
    const int tg   = lane & 3;       // 0..3
    const int row0 = blockIdx.x * 128;

    // ---- Stage weights in fragment-packed order (cooperative) ----
    #pragma unroll
    for (int l = 0; l < 2; l++) {
        const float* W = l ? Wo_g : Wh_g;
        #pragma unroll
        for (int ii = 0; ii < 8; ii++) {
            int i = tid + ii * 256;          // 0..2047
            int ln = i & 31;
            int nt = (i >> 5) & 7;
            int s  = i >> 8;                 // 0..7
            int tgg = ln & 3, gg = ln >> 2;
            // layer 1: k-slot (s,tgg) holds TRUE rows 16*tgg + 2s (+1)
            // layer 2: k-slot (s,tgg) holds TRUE rows 8s + 2*tgg (+1)
            int r = l ? (8 * s + 2 * tgg) : (16 * tgg + 2 * s);
            int n = nt * 8 + gg;
            Wp[l * 4096 + 2 * i]     = f2tf32(__ldg(&W[r * 64 + n]));
            Wp[l * 4096 + 2 * i + 1] = f2tf32(__ldg(&W[(r + 1) * 64 + n]));
        }
    }
    __syncthreads();   // the only block barrier

    // ---- Warp-per-node gather into own Ts stripe ----
    for (int rr = 0; rr < 16; rr++) {
        int lr = warp * 16 + rr;
        int v  = row0 + lr;
        float ax = 0.f, ay = 0.f;
        if (v < N_NODES) {
            float2 xs = __ldg(&X2[(size_t)v * 32 + lane]);   // self term
            ax = xs.x; ay = xs.y;
            int d = 0;
            if (lane == 0) {
                d = g_cnt[v];
                g_cnt[v] = 0;                 // reset for next replay
            }
            d = __shfl_sync(0xffffffffu, d, 0);
            d = min(d, MAXD);
            const int* ap = &g_adj[(size_t)v * MAXD];
            for (int base = 0; base < d; base += 32) {
                int rem = min(d - base, 32);
                int u = 0;
                if (lane < rem) u = __ldg(&ap[base + lane]);
                int j = 0;
                for (; j + 4 <= rem; j += 4) {
                    int u0 = __shfl_sync(0xffffffffu, u, j);
                    int u1 = __shfl_sync(0xffffffffu, u, j + 1);
                    int u2 = __shfl_sync(0xffffffffu, u, j + 2);
                    int u3 = __shfl_sync(0xffffffffu, u, j + 3);
                    float2 x0 = __ldg(&X2[(size_t)u0 * 32 + lane]);
                    float2 x1 = __ldg(&X2[(size_t)u1 * 32 + lane]);
                    float2 x2 = __ldg(&X2[(size_t)u2 * 32 + lane]);
                    float2 x3 = __ldg(&X2[(size_t)u3 * 32 + lane]);
                    ax += x0.x + x1.x + x2.x + x3.x;
                    ay += x0.y + x1.y + x2.y + x3.y;
                }
                for (; j < rem; j++) {
                    int uu = __shfl_sync(0xffffffffu, u, j);
                    float2 xv = __ldg(&X2[(size_t)uu * 32 + lane]);
                    ax += xv.x;
                    ay += xv.y;
                }
            }
        }
        *(uint2*)&Ts[lr * TS + 2 * lane] = make_uint2(f2tf32(ax), f2tf32(ay));
    }
    __syncwarp();   // warp's fragment rows are exactly the rows it gathered

    // ---- Pull A fragments: 4x LDS.128 per row, own warp stripe ----
    const int lr0 = warp * 16 + g;
    const int lr1 = lr0 + 8;
    unsigned a0r[16], a1r[16];       // [j] = phys col 16*tg + j
    #pragma unroll
    for (int q = 0; q < 4; q++) {
        *(uint4*)&a0r[4 * q] = *(const uint4*)&Ts[lr0 * TS + tg * 16 + 4 * q];
        *(uint4*)&a1r[4 * q] = *(const uint4*)&Ts[lr1 * TS + tg * 16 + 4 * q];
    }

    // ================= Layer 1 =================
    float acc[8][4];
    #pragma unroll
    for (int nt = 0; nt < 8; nt++) {
        float blo = __ldg(&bh[nt * 8 + 2 * tg]);
        float bhi = __ldg(&bh[nt * 8 + 2 * tg + 1]);
        acc[nt][0] = blo; acc[nt][1] = bhi; acc[nt][2] = blo; acc[nt][3] = bhi;
    }
    #pragma unroll
    for (int s = 0; s < 8; s++) {
        unsigned A0 = a0r[2 * s], A2 = a0r[2 * s + 1];
        unsigned A1 = a1r[2 * s], A3 = a1r[2 * s + 1];
        #pragma unroll
        for (int nt = 0; nt < 8; nt++) {
            uint2 b = *(const uint2*)&Wp[((s * 8 + nt) * 32 + lane) * 2];
            mma_tf32(acc[nt], A0, A1, A2, A3, b.x, b.y);
        }
    }

    // ---- relu + cvt: accumulators become layer-2 A fragments directly ----
    unsigned h0[8], h1[8], h2[8], h3[8];
    #pragma unroll
    for (int s = 0; s < 8; s++) {
        h0[s] = f2tf32(fmaxf(acc[s][0], 0.f));
        h1[s] = f2tf32(fmaxf(acc[s][2], 0.f));
        h2[s] = f2tf32(fmaxf(acc[s][1], 0.f));
        h3[s] = f2tf32(fmaxf(acc[s][3], 0.f));
    }

    // ================= Layer 2 =================
    #pragma unroll
    for (int nt = 0; nt < 8; nt++) {
        float blo = __ldg(&bo[nt * 8 + 2 * tg]);
        float bhi = __ldg(&bo[nt * 8 + 2 * tg + 1]);
        acc[nt][0] = blo; acc[nt][1] = bhi; acc[nt][2] = blo; acc[nt][3] = bhi;
    }
    #pragma unroll
    for (int s = 0; s < 8; s++) {
        #pragma unroll
        for (int nt = 0; nt < 8; nt++) {
            uint2 b = *(const uint2*)&Wp[4096 + ((s * 8 + nt) * 32 + lane) * 2];
            mma_tf32(acc[nt], h0[s], h1[s], h2[s], h3[s], b.x, b.y);
        }
    }

    // ---- Epilogue: relu + direct STG.64 ----
    const int r0 = row0 + lr0;
    const int r1 = row0 + lr1;
    #pragma unroll
    for (int nt = 0; nt < 8; nt++) {
        int c = nt * 8 + 2 * tg;
        if (r0 < N_NODES) {
            float2 v = make_float2(fmaxf(acc[nt][0], 0.f), fmaxf(acc[nt][1], 0.f));
            *(float2*)&out[(size_t)r0 * 64 + c] = v;
        }
        if (r1 < N_NODES) {
            float2 v = make_float2(fmaxf(acc[nt][2], 0.f), fmaxf(acc[nt][3], 0.f));
            *(float2*)&out[(size_t)r1 * 64 + c] = v;
        }
    }
}

// ---------------------------------------------------------------------------
// Inputs: 0=X, 1=ref_a, 2=ref_b, 3=v_map(unused), 4=v_count(unused),
//         5=W_hidden, 6=b_hidden, 7=W_out, 8=b_out
// ---------------------------------------------------------------------------
extern "C" void kernel_launch(void* const* d_in, const int* in_sizes, int n_in,
                              void* d_out, int out_size) {
    const float* X   = (const float*)d_in[0];
    const int* ref_a = (const int*)d_in[1];
    const int* ref_b = (const int*)d_in[2];
    const float* Wh  = (const float*)d_in[5];
    const float* bh  = (const float*)d_in[6];
    const float* Wo  = (const float*)d_in[7];
    const float* bo  = (const float*)d_in[8];
    float* out = (float*)d_out;

    // 1) bucket adjacency (g_cnt zero-invariant maintained by k_gin)
    k_fill<<<(N_EDGES / 4 + 255) / 256, 256>>>((const int4*)ref_a,
                                               (const int4*)ref_b);

    // 2) fused warp-gather + TF32 MLP
    cudaFuncSetAttribute(k_gin, cudaFuncAttributeMaxDynamicSharedMemorySize,
                         GIN_SMEM);
    int blocks = (N_NODES + 127) / 128;   // 782
    k_gin<<<blocks, 256, GIN_SMEM>>>((const float2*)X, Wh, bh, Wo, bo, out);
}

// round 7
// speedup vs baseline: 1.1022x; 1.1022x over previous
#include <cuda_runtime.h>
#include <cuda_bf16.h>

#define N_NODES 100000
#define N_EDGES 1000000
#define D_FEAT  64
#define MAXD    96

// Adjacency buckets. g_cnt zero-initialized at load; k_gin resets each node's
// counter after consuming it, so every graph replay sees identical state.
__device__ int g_cnt[N_NODES];
__device__ int g_adj[(size_t)N_NODES * MAXD];

// ---------------------------------------------------------------------------
// Fill: bucket both directions of each edge. int4-vectorized edge reads.
// ---------------------------------------------------------------------------
__global__ void k_fill(const int4* __restrict__ ra4, const int4* __restrict__ rb4) {
    int i = blockIdx.x * blockDim.x + threadIdx.x;
    if (i >= N_EDGES / 4) return;
    int4 a4 = __ldg(&ra4[i]);
    int4 b4 = __ldg(&rb4[i]);
    int as[4] = {a4.x, a4.y, a4.z, a4.w};
    int bs[4] = {b4.x, b4.y, b4.z, b4.w};
    #pragma unroll
    for (int j = 0; j < 4; j++) {
        int a = as[j], b = bs[j];
        int pa = atomicAdd(&g_cnt[a], 1);
        if (pa < MAXD) g_adj[(size_t)a * MAXD + pa] = b;
        int pb = atomicAdd(&g_cnt[b], 1);
        if (pb < MAXD) g_adj[(size_t)b * MAXD + pb] = a;
    }
}

// ---------------------------------------------------------------------------
// Fused gather + register-fragment TF32 MLP:
//   out = relu(relu((X[v] + sum_nbr X[u]) @ Wh + bh) @ Wo + bo)
// 256 threads = 8 warps; warp w owns local rows [16w, 16w+16).
// Gather: half-warp per neighbor (p = lane>=16 picks interleaved neighbors,
//         q = lane&15 is the float4 column) -> fully coalesced 256B row reads,
//         uniform-address index loads (no shfl), unroll-4 deferred adds so 4
//         row-loads stay in flight per half; one shfl_xor(16) combine per node.
// MMA:    k-permuted A fragments from own Ts stripe (syncwarp only);
//         layer-1 accumulators ARE the layer-2 A fragment (W2 rows permuted);
//         weights packed pairwise -> one LDS.128 per (s, nt-pair).
// ---------------------------------------------------------------------------
#define TS 68
#define GIN_SMEM ((2 * 4096 + 128 * TS) * 4)   // Wp + Ts = 67584 bytes

__device__ __forceinline__ unsigned f2tf32(float f) {
    unsigned u;
    asm("cvt.rna.tf32.f32 %0, %1;" : "=r"(u) : "f"(f));
    return u;
}

__device__ __forceinline__ void mma_tf32(float* d, unsigned a0, unsigned a1,
                                         unsigned a2, unsigned a3,
                                         unsigned b0, unsigned b1) {
    asm volatile(
        "mma.sync.aligned.m16n8k8.row.col.f32.tf32.tf32.f32 "
        "{%0,%1,%2,%3}, {%4,%5,%6,%7}, {%8,%9}, {%0,%1,%2,%3};\n"
        : "+f"(d[0]), "+f"(d[1]), "+f"(d[2]), "+f"(d[3])
        : "r"(a0), "r"(a1), "r"(a2), "r"(a3), "r"(b0), "r"(b1));
}

__device__ __forceinline__ void acc4(float4& a, float4 x) {
    a.x += x.x; a.y += x.y; a.z += x.z; a.w += x.w;
}

__global__ __launch_bounds__(256, 3)
void k_gin(const float4* __restrict__ X4,
           const float* __restrict__ Wh_g, const float* __restrict__ bh,
           const float* __restrict__ Wo_g, const float* __restrict__ bo,
           float* __restrict__ out) {
    extern __shared__ unsigned sm[];
    unsigned* Wp = sm;              // [2][4096] packed weight fragments (paired nt)
    unsigned* Ts = sm + 8192;       // [128][TS] aggregated tile (tf32)

    const int tid  = threadIdx.x;
    const int lane = tid & 31;
    const int warp = tid >> 5;
    const int g    = lane >> 2;      // 0..7   (mma row group)
    const int tg   = lane & 3;       // 0..3   (mma thread-in-group)
    const int p    = lane >> 4;      // 0..1   (gather half)
    const int q    = lane & 15;      // 0..15  (gather float4 column)
    const int row0 = blockIdx.x * 128;

    // ---- Stage weights, fragment-packed with nt pairs for LDS.128 ----
    // Slot (l, s, np, lane) at Wp[l*4096 + ((s*4+np)*32+lane)*4]:
    //   words {0,1} = B-frag for nt=2np, words {2,3} = nt=2np+1.
    #pragma unroll
    for (int l = 0; l < 2; l++) {
        const float* W = l ? Wo_g : Wh_g;
        #pragma unroll
        for (int ii = 0; ii < 4; ii++) {
            int i = tid + ii * 256;          // 0..1023 slots
            int ln = i & 31;
            int np = (i >> 5) & 3;
            int s  = i >> 7;                 // 0..7
            int tgg = ln & 3, gg = ln >> 2;
            // layer 1: k-slot (s,tgg) holds TRUE rows 16*tgg + 2s (+1)
            // layer 2: k-slot (s,tgg) holds TRUE rows 8s + 2*tgg (+1)
            int r = l ? (8 * s + 2 * tgg) : (16 * tgg + 2 * s);
            unsigned* dst = &Wp[l * 4096 + i * 4];
            int n0 = (2 * np) * 8 + gg;
            int n1 = (2 * np + 1) * 8 + gg;
            dst[0] = f2tf32(__ldg(&W[r * 64 + n0]));
            dst[1] = f2tf32(__ldg(&W[(r + 1) * 64 + n0]));
            dst[2] = f2tf32(__ldg(&W[r * 64 + n1]));
            dst[3] = f2tf32(__ldg(&W[(r + 1) * 64 + n1]));
        }
    }
    __syncthreads();   // the only block barrier

    // ---- Warp-per-node gather into own Ts stripe ----
    for (int rr = 0; rr < 16; rr++) {
        int lr = warp * 16 + rr;
        int v  = row0 + lr;
        float4 acc = make_float4(0.f, 0.f, 0.f, 0.f);
        if (v < N_NODES) {
            // self term counted once (half 0 only)
            if (p == 0) acc = __ldg(&X4[(size_t)v * 16 + q]);
            int d = min(g_cnt[v], MAXD);     // uniform address -> broadcast
            if (lane == 0) g_cnt[v] = 0;     // reset for next replay
            const int* ap = &g_adj[(size_t)v * MAXD];
            int i = p;
            // unroll-4: keep 4 independent row loads in flight per half
            for (; i + 6 < d; i += 8) {
                int u0 = __ldg(&ap[i]);
                int u1 = __ldg(&ap[i + 2]);
                int u2 = __ldg(&ap[i + 4]);
                int u3 = __ldg(&ap[i + 6]);
                float4 x0 = __ldg(&X4[(size_t)u0 * 16 + q]);
                float4 x1 = __ldg(&X4[(size_t)u1 * 16 + q]);
                float4 x2 = __ldg(&X4[(size_t)u2 * 16 + q]);
                float4 x3 = __ldg(&X4[(size_t)u3 * 16 + q]);
                acc4(acc, x0); acc4(acc, x1); acc4(acc, x2); acc4(acc, x3);
            }
            for (; i < d; i += 2) {
                int u = __ldg(&ap[i]);
                float4 x = __ldg(&X4[(size_t)u * 16 + q]);
                acc4(acc, x);
            }
        }
        // combine the two halves (same column layout, disjoint neighbor sets)
        acc.x += __shfl_xor_sync(0xffffffffu, acc.x, 16);
        acc.y += __shfl_xor_sync(0xffffffffu, acc.y, 16);
        acc.z += __shfl_xor_sync(0xffffffffu, acc.z, 16);
        acc.w += __shfl_xor_sync(0xffffffffu, acc.w, 16);
        if (p == 0) {
            uint4 st = make_uint4(f2tf32(acc.x), f2tf32(acc.y),
                                  f2tf32(acc.z), f2tf32(acc.w));
            *(uint4*)&Ts[lr * TS + 4 * q] = st;
        }
    }
    __syncwarp();   // warp's fragment rows are exactly the rows it gathered

    // ---- Pull A fragments: 4x LDS.128 per row, own warp stripe ----
    const int lr0 = warp * 16 + g;
    const int lr1 = lr0 + 8;
    unsigned a0r[16], a1r[16];       // [j] = phys col 16*tg + j
    #pragma unroll
    for (int qq = 0; qq < 4; qq++) {
        *(uint4*)&a0r[4 * qq] = *(const uint4*)&Ts[lr0 * TS + tg * 16 + 4 * qq];
        *(uint4*)&a1r[4 * qq] = *(const uint4*)&Ts[lr1 * TS + tg * 16 + 4 * qq];
    }

    // ================= Layer 1 =================
    float acc[8][4];
    #pragma unroll
    for (int nt = 0; nt < 8; nt++) {
        float blo = __ldg(&bh[nt * 8 + 2 * tg]);
        float bhi = __ldg(&bh[nt * 8 + 2 * tg + 1]);
        acc[nt][0] = blo; acc[nt][1] = bhi; acc[nt][2] = blo; acc[nt][3] = bhi;
    }
    #pragma unroll
    for (int s = 0; s < 8; s++) {
        unsigned A0 = a0r[2 * s], A2 = a0r[2 * s + 1];
        unsigned A1 = a1r[2 * s], A3 = a1r[2 * s + 1];
        #pragma unroll
        for (int np = 0; np < 4; np++) {
            uint4 b = *(const uint4*)&Wp[((s * 4 + np) * 32 + lane) * 4];
            mma_tf32(acc[2 * np],     A0, A1, A2, A3, b.x, b.y);
            mma_tf32(acc[2 * np + 1], A0, A1, A2, A3, b.z, b.w);
        }
    }

    // ---- relu + cvt: accumulators become layer-2 A fragments directly ----
    unsigned h0[8], h1[8], h2[8], h3[8];
    #pragma unroll
    for (int s = 0; s < 8; s++) {
        h0[s] = f2tf32(fmaxf(acc[s][0], 0.f));
        h1[s] = f2tf32(fmaxf(acc[s][2], 0.f));
        h2[s] = f2tf32(fmaxf(acc[s][1], 0.f));
        h3[s] = f2tf32(fmaxf(acc[s][3], 0.f));
    }

    // ================= Layer 2 =================
    #pragma unroll
    for (int nt = 0; nt < 8; nt++) {
        float blo = __ldg(&bo[nt * 8 + 2 * tg]);
        float bhi = __ldg(&bo[nt * 8 + 2 * tg + 1]);
        acc[nt][0] = blo; acc[nt][1] = bhi; acc[nt][2] = blo; acc[nt][3] = bhi;
    }
    #pragma unroll
    for (int s = 0; s < 8; s++) {
        #pragma unroll
        for (int np = 0; np < 4; np++) {
            uint4 b = *(const uint4*)&Wp[4096 + ((s * 4 + np) * 32 + lane) * 4];
            mma_tf32(acc[2 * np],     h0[s], h1[s], h2[s], h3[s], b.x, b.y);
            mma_tf32(acc[2 * np + 1], h0[s], h1[s], h2[s], h3[s], b.z, b.w);
        }
    }

    // ---- Epilogue: relu + direct STG.64 ----
    const int r0 = row0 + lr0;
    const int r1 = row0 + lr1;
    #pragma unroll
    for (int nt = 0; nt < 8; nt++) {
        int c = nt * 8 + 2 * tg;
        if (r0 < N_NODES) {
            float2 v = make_float2(fmaxf(acc[nt][0], 0.f), fmaxf(acc[nt][1], 0.f));
            *(float2*)&out[(size_t)r0 * 64 + c] = v;
        }
        if (r1 < N_NODES) {
            float2 v = make_float2(fmaxf(acc[nt][2], 0.f), fmaxf(acc[nt][3], 0.f));
            *(float2*)&out[(size_t)r1 * 64 + c] = v;
        }
    }
}

// ---------------------------------------------------------------------------
// Inputs: 0=X, 1=ref_a, 2=ref_b, 3=v_map(unused), 4=v_count(unused),
//         5=W_hidden, 6=b_hidden, 7=W_out, 8=b_out
// ---------------------------------------------------------------------------
extern "C" void kernel_launch(void* const* d_in, const int* in_sizes, int n_in,
                              void* d_out, int out_size) {
    const float* X   = (const float*)d_in[0];
    const int* ref_a = (const int*)d_in[1];
    const int* ref_b = (const int*)d_in[2];
    const float* Wh  = (const float*)d_in[5];
    const float* bh  = (const float*)d_in[6];
    const float* Wo  = (const float*)d_in[7];
    const float* bo  = (const float*)d_in[8];
    float* out = (float*)d_out;

    // 1) bucket adjacency (g_cnt zero-invariant maintained by k_gin)
    k_fill<<<(N_EDGES / 4 + 255) / 256, 256>>>((const int4*)ref_a,
                                               (const int4*)ref_b);

    // 2) fused half-warp gather + TF32 MLP
    cudaFuncSetAttribute(k_gin, cudaFuncAttributeMaxDynamicSharedMemorySize,
                         GIN_SMEM);
    int blocks = (N_NODES + 127) / 128;   // 782
    k_gin<<<blocks, 256, GIN_SMEM>>>((const float4*)X, Wh, bh, Wo, bo, out);
}

// round 9
// speedup vs baseline: 1.7650x; 1.6013x over previous
#include <cuda_runtime.h>
#include <cuda_bf16.h>

#define N_NODES 100000
#define N_EDGES 1000000
#define D_FEAT  64

// Neighbor-sum accumulator. Zero-initialized at module load; k_mlp re-zeroes
// its tile after consuming, so every graph replay sees zeros (deterministic).
__device__ float g_agg[N_NODES * D_FEAT];

// ---------------------------------------------------------------------------
// Edge scatter: 16 threads per edge, one float4 chunk each, both directions.
// Bound by the L2 REDG op rate (~83us) — at the hardware floor for scatter.
// ---------------------------------------------------------------------------
__device__ __forceinline__ void red_add_v4(float* addr, float4 v) {
    asm volatile("red.global.add.v4.f32 [%0], {%1, %2, %3, %4};"
                 :: "l"(addr), "f"(v.x), "f"(v.y), "f"(v.z), "f"(v.w)
                 : "memory");
}

__global__ void k_scatter(const float4* __restrict__ X4,
                          const int* __restrict__ ref_a,
                          const int* __restrict__ ref_b) {
    unsigned t = blockIdx.x * blockDim.x + threadIdx.x;
    unsigned e = t >> 4;
    unsigned c = t & 15;
    if (e >= N_EDGES) return;
    int a = __ldg(&ref_a[e]);
    int b = __ldg(&ref_b[e]);
    const int F4 = D_FEAT / 4;   // 16
    float4 xb = __ldg(&X4[(size_t)b * F4 + c]);
    float4 xa = __ldg(&X4[(size_t)a * F4 + c]);
    red_add_v4(&g_agg[((size_t)a * F4 + c) * 4], xb);
    red_add_v4(&g_agg[((size_t)b * F4 + c) * 4], xa);
}

// ---------------------------------------------------------------------------
// Register-fragment TF32 MLP, warp-private smem staging:
//   out = relu(relu((X+agg) @ Wh + bh) @ Wo + bo)
// 256 threads = 8 warps; warp w privately owns Ts rows [16w, 16w+16) for
// ingress, fragment pulls, egress staging and global stores -> syncwarp only.
//   layer-1: phys col 16t+j <-> logical k = t+4j (thread tg owns its quarter)
//   layer-2: layer-1 accumulators ARE the layer-2 A fragment (W2 rows permuted)
//   weights packed pairwise -> one LDS.128 per (s, nt-pair)
// NOTE: agg is read AND zeroed through ONE non-restrict pointer with an
// explicit compiler barrier between — the same buffer through two __restrict__
// params let ptxas hoist the zero-stores above the loads (round-8 bug).
// ---------------------------------------------------------------------------
#define TS 68
#define MLP_SMEM ((2 * 4096 + 128 * TS) * 4)   // Wp + Ts = 67584 bytes

__device__ __forceinline__ unsigned f2tf32(float f) {
    unsigned u;
    asm("cvt.rna.tf32.f32 %0, %1;" : "=r"(u) : "f"(f));
    return u;
}

__device__ __forceinline__ void mma_tf32(float* d, unsigned a0, unsigned a1,
                                         unsigned a2, unsigned a3,
                                         unsigned b0, unsigned b1) {
    asm volatile(
        "mma.sync.aligned.m16n8k8.row.col.f32.tf32.tf32.f32 "
        "{%0,%1,%2,%3}, {%4,%5,%6,%7}, {%8,%9}, {%0,%1,%2,%3};\n"
        : "+f"(d[0]), "+f"(d[1]), "+f"(d[2]), "+f"(d[3])
        : "r"(a0), "r"(a1), "r"(a2), "r"(a3), "r"(b0), "r"(b1));
}

__global__ __launch_bounds__(256)
void k_mlp(float4* agg4,                       // read + zeroed (NOT restrict)
           const float4* __restrict__ X4,
           const float* __restrict__ Wh_g, const float* __restrict__ bh,
           const float* __restrict__ Wo_g, const float* __restrict__ bo,
           float4* __restrict__ out4) {
    extern __shared__ unsigned sm[];
    unsigned* Wp = sm;              // [2][4096] packed weight fragments (paired nt)
    unsigned* Ts = sm + 8192;       // [128][TS] warp-private staging stripes

    const int tid  = threadIdx.x;
    const int lane = tid & 31;
    const int warp = tid >> 5;
    const int g    = lane >> 2;      // 0..7
    const int tg   = lane & 3;       // 0..3
    const int row0 = blockIdx.x * 128;

    // ---- Stage weights, fragment-packed with nt pairs for LDS.128 ----
    #pragma unroll
    for (int l = 0; l < 2; l++) {
        const float* W = l ? Wo_g : Wh_g;
        #pragma unroll
        for (int ii = 0; ii < 4; ii++) {
            int i = tid + ii * 256;          // 0..1023 slots
            int ln = i & 31;
            int np = (i >> 5) & 3;
            int s  = i >> 7;                 // 0..7
            int tgg = ln & 3, gg = ln >> 2;
            // layer 1: k-slot (s,tgg) holds TRUE rows 16*tgg + 2s (+1)
            // layer 2: k-slot (s,tgg) holds TRUE rows 8s + 2*tgg (+1)
            int r = l ? (8 * s + 2 * tgg) : (16 * tgg + 2 * s);
            unsigned* dst = &Wp[l * 4096 + i * 4];
            int n0 = (2 * np) * 8 + gg;
            int n1 = (2 * np + 1) * 8 + gg;
            dst[0] = f2tf32(__ldg(&W[r * 64 + n0]));
            dst[1] = f2tf32(__ldg(&W[(r + 1) * 64 + n0]));
            dst[2] = f2tf32(__ldg(&W[r * 64 + n1]));
            dst[3] = f2tf32(__ldg(&W[(r + 1) * 64 + n1]));
        }
    }
    __syncthreads();   // the only block barrier

    // ---- Per-warp coalesced ingress: own 16 rows of tf32(X + agg) ----
    #pragma unroll
    for (int i = 0; i < 8; i++) {
        int idx = i * 32 + lane;             // 0..255 float4 within warp tile
        int r  = warp * 16 + (idx >> 4);     // local row (warp-private)
        int c4 = idx & 15;
        int grow = row0 + r;
        uint4 st = make_uint4(0u, 0u, 0u, 0u);
        if (grow < N_NODES) {
            float4 a = agg4[(size_t)grow * 16 + c4];
            float4 x = __ldg(&X4[(size_t)grow * 16 + c4]);
            st.x = f2tf32(a.x + x.x);
            st.y = f2tf32(a.y + x.y);
            st.z = f2tf32(a.z + x.z);
            st.w = f2tf32(a.w + x.w);
        }
        *(uint4*)&Ts[r * TS + c4 * 4] = st;
    }

    // Compiler barrier: all agg loads above must be materialized before the
    // zero stores below (same buffer!).
    asm volatile("" ::: "memory");

    // Re-zero own agg rows (fire-and-forget coalesced stores).
    {
        const float4 z4 = make_float4(0.f, 0.f, 0.f, 0.f);
        #pragma unroll
        for (int i = 0; i < 8; i++) {
            int idx = i * 32 + lane;
            int grow = row0 + warp * 16 + (idx >> 4);
            if (grow < N_NODES)
                agg4[(size_t)grow * 16 + (idx & 15)] = z4;
        }
    }
    __syncwarp();

    // ---- Pull A fragments: 4x LDS.128 per row, own warp stripe ----
    const int lr0 = warp * 16 + g;
    const int lr1 = lr0 + 8;
    unsigned a0r[16], a1r[16];       // [j] = phys col 16*tg + j
    #pragma unroll
    for (int qq = 0; qq < 4; qq++) {
        *(uint4*)&a0r[4 * qq] = *(const uint4*)&Ts[lr0 * TS + tg * 16 + 4 * qq];
        *(uint4*)&a1r[4 * qq] = *(const uint4*)&Ts[lr1 * TS + tg * 16 + 4 * qq];
    }

    // ================= Layer 1 =================
    float acc[8][4];
    #pragma unroll
    for (int nt = 0; nt < 8; nt++) {
        float blo = __ldg(&bh[nt * 8 + 2 * tg]);
        float bhi = __ldg(&bh[nt * 8 + 2 * tg + 1]);
        acc[nt][0] = blo; acc[nt][1] = bhi; acc[nt][2] = blo; acc[nt][3] = bhi;
    }
    #pragma unroll
    for (int s = 0; s < 8; s++) {
        unsigned A0 = a0r[2 * s], A2 = a0r[2 * s + 1];
        unsigned A1 = a1r[2 * s], A3 = a1r[2 * s + 1];
        #pragma unroll
        for (int np = 0; np < 4; np++) {
            uint4 b = *(const uint4*)&Wp[((s * 4 + np) * 32 + lane) * 4];
            mma_tf32(acc[2 * np],     A0, A1, A2, A3, b.x, b.y);
            mma_tf32(acc[2 * np + 1], A0, A1, A2, A3, b.z, b.w);
        }
    }

    // ---- relu + cvt: accumulators become layer-2 A fragments directly ----
    unsigned h0[8], h1[8], h2[8], h3[8];
    #pragma unroll
    for (int s = 0; s < 8; s++) {
        h0[s] = f2tf32(fmaxf(acc[s][0], 0.f));
        h1[s] = f2tf32(fmaxf(acc[s][2], 0.f));
        h2[s] = f2tf32(fmaxf(acc[s][1], 0.f));
        h3[s] = f2tf32(fmaxf(acc[s][3], 0.f));
    }

    // ================= Layer 2 =================
    #pragma unroll
    for (int nt = 0; nt < 8; nt++) {
        float blo = __ldg(&bo[nt * 8 + 2 * tg]);
        float bhi = __ldg(&bo[nt * 8 + 2 * tg + 1]);
        acc[nt][0] = blo; acc[nt][1] = bhi; acc[nt][2] = blo; acc[nt][3] = bhi;
    }
    #pragma unroll
    for (int s = 0; s < 8; s++) {
        #pragma unroll
        for (int np = 0; np < 4; np++) {
            uint4 b = *(const uint4*)&Wp[4096 + ((s * 4 + np) * 32 + lane) * 4];
            mma_tf32(acc[2 * np],     h0[s], h1[s], h2[s], h3[s], b.x, b.y);
            mma_tf32(acc[2 * np + 1], h0[s], h1[s], h2[s], h3[s], b.z, b.w);
        }
    }

    // ---- Egress: relu -> own warp stripe (warp-private, syncwarp only) ----
    #pragma unroll
    for (int nt = 0; nt < 8; nt++) {
        int c = nt * 8 + 2 * tg;
        *(uint2*)&Ts[lr0 * TS + c] = make_uint2(
            __float_as_uint(fmaxf(acc[nt][0], 0.f)),
            __float_as_uint(fmaxf(acc[nt][1], 0.f)));
        *(uint2*)&Ts[lr1 * TS + c] = make_uint2(
            __float_as_uint(fmaxf(acc[nt][2], 0.f)),
            __float_as_uint(fmaxf(acc[nt][3], 0.f)));
    }
    __syncwarp();

    // ---- Per-warp coalesced STG.128 of own 16 output rows ----
    #pragma unroll
    for (int i = 0; i < 8; i++) {
        int idx = i * 32 + lane;
        int r  = warp * 16 + (idx >> 4);
        int c4 = idx & 15;
        int grow = row0 + r;
        if (grow < N_NODES) {
            uint4 v = *(const uint4*)&Ts[r * TS + c4 * 4];
            out4[(size_t)grow * 16 + c4] = make_float4(
                __uint_as_float(v.x), __uint_as_float(v.y),
                __uint_as_float(v.z), __uint_as_float(v.w));
        }
    }
}

// ---------------------------------------------------------------------------
// Inputs: 0=X, 1=ref_a, 2=ref_b, 3=v_map(unused), 4=v_count(unused),
//         5=W_hidden, 6=b_hidden, 7=W_out, 8=b_out
// ---------------------------------------------------------------------------
extern "C" void kernel_launch(void* const* d_in, const int* in_sizes, int n_in,
                              void* d_out, int out_size) {
    const float* X   = (const float*)d_in[0];
    const int* ref_a = (const int*)d_in[1];
    const int* ref_b = (const int*)d_in[2];
    const float* Wh  = (const float*)d_in[5];
    const float* bh  = (const float*)d_in[6];
    const float* Wo  = (const float*)d_in[7];
    const float* bo  = (const float*)d_in[8];
    float* out = (float*)d_out;

    float* agg;
    cudaGetSymbolAddress((void**)&agg, g_agg);

    // 1) edge scatter into zeroed agg (zero-invariant maintained by k_mlp)
    {
        long long total = (long long)N_EDGES * 16;
        int blocks = (int)((total + 255) / 256);
        k_scatter<<<blocks, 256>>>((const float4*)X, ref_a, ref_b);
    }

    // 2) register-fragment TF32 MLP, warp-private staging
    {
        cudaFuncSetAttribute(k_mlp, cudaFuncAttributeMaxDynamicSharedMemorySize,
                             MLP_SMEM);
        int blocks = (N_NODES + 127) / 128;   // 782
        k_mlp<<<blocks, 256, MLP_SMEM>>>((float4*)agg, (const float4*)X,
                                         Wh, bh, Wo, bo, (float4*)out);
    }
}

// round 10
// speedup vs baseline: 1.8707x; 1.0599x over previous
#include <cuda_runtime.h>
#include <cuda_fp16.h>

#define N_NODES 100000
#define N_EDGES 1000000
#define D_FEAT  64

// Neighbor-sum accumulator. Zero-initialized at module load; k_mlp re-zeroes
// its tile after consuming, so every graph replay sees zeros (deterministic).
__device__ float g_agg[N_NODES * D_FEAT];

// ---------------------------------------------------------------------------
// Edge scatter: 16 threads per edge, one float4 chunk each, both directions.
// Bound by the L2 REDG/byte rate (~80us) — at the hardware floor for scatter.
// ---------------------------------------------------------------------------
__device__ __forceinline__ void red_add_v4(float* addr, float4 v) {
    asm volatile("red.global.add.v4.f32 [%0], {%1, %2, %3, %4};"
                 :: "l"(addr), "f"(v.x), "f"(v.y), "f"(v.z), "f"(v.w)
                 : "memory");
}

__global__ void k_scatter(const float4* __restrict__ X4,
                          const int* __restrict__ ref_a,
                          const int* __restrict__ ref_b) {
    unsigned t = blockIdx.x * blockDim.x + threadIdx.x;
    unsigned e = t >> 4;
    unsigned c = t & 15;
    if (e >= N_EDGES) return;
    int a = __ldg(&ref_a[e]);
    int b = __ldg(&ref_b[e]);
    const int F4 = D_FEAT / 4;   // 16
    float4 xb = __ldg(&X4[(size_t)b * F4 + c]);
    float4 xa = __ldg(&X4[(size_t)a * F4 + c]);
    red_add_v4(&g_agg[((size_t)a * F4 + c) * 4], xb);
    red_add_v4(&g_agg[((size_t)b * F4 + c) * 4], xa);
}

// ---------------------------------------------------------------------------
// FP16 m16n8k16 register-fragment MLP (fp32 accumulate), warp-private staging:
//   out = relu(relu((X+agg) @ Wh + bh) @ Wo + bo)
// 256 threads = 8 warps; warp w privately owns Ts rows [16w, 16w+16).
// k-permutation (layer 1): thread tg owns phys cols [16tg,16tg+16); mma step s
//   slot0 = phys cols 16tg+4s+{0,1}, slot1 = +{2,3}; W1 rows permuted to match.
// Chaining (layer 2): layer-1 accumulators (cols 8nt+2tg) become the layer-2
//   A fragment with step s: slot0 <- nt=2s (cols 16s+2tg), slot1 <- nt=2s+1;
//   W2 rows permuted as 16s + 8*slot + 2*tg.
// Weights packed per (layer, step, nt-pair): one LDS.128 supplies 2 mmas.
// ---------------------------------------------------------------------------
#define TSW 72                                  // Ts row stride in 32-bit words
#define MLP_SMEM ((4096 + 128 * TSW) * 4)       // Wp 16KB + Ts 36KB = 52.0KB

__device__ __forceinline__ unsigned h2(float lo, float hi) {
    __half2 h = __floats2half2_rn(lo, hi);
    return *(unsigned*)&h;
}

__device__ __forceinline__ void mma_f16(float* d, unsigned a0, unsigned a1,
                                        unsigned a2, unsigned a3,
                                        unsigned b0, unsigned b1) {
    asm volatile(
        "mma.sync.aligned.m16n8k16.row.col.f32.f16.f16.f32 "
        "{%0,%1,%2,%3}, {%4,%5,%6,%7}, {%8,%9}, {%0,%1,%2,%3};\n"
        : "+f"(d[0]), "+f"(d[1]), "+f"(d[2]), "+f"(d[3])
        : "r"(a0), "r"(a1), "r"(a2), "r"(a3), "r"(b0), "r"(b1));
}

__global__ __launch_bounds__(256, 3)
void k_mlp(float4* agg4,                        // read + zeroed (NOT restrict)
           const float4* __restrict__ X4,
           const float* __restrict__ Wh_g, const float* __restrict__ bh,
           const float* __restrict__ Wo_g, const float* __restrict__ bo,
           float4* __restrict__ out4) {
    extern __shared__ unsigned sm[];
    unsigned* Wp = sm;              // [2][2048] packed fp16 weight fragments
    unsigned* Ts = sm + 4096;       // [128][TSW] warp-private staging

    const int tid  = threadIdx.x;
    const int lane = tid & 31;
    const int warp = tid >> 5;
    const int g    = lane >> 2;      // 0..7
    const int tg   = lane & 3;       // 0..3
    const int row0 = blockIdx.x * 128;

    // ---- Stage weights: slot (l, s, np, lane), 4 words per slot:
    //   words {0,1} = b0,b1 for nt=2np ; words {2,3} = b0,b1 for nt=2np+1.
    #pragma unroll
    for (int l = 0; l < 2; l++) {
        const float* W = l ? Wo_g : Wh_g;
        #pragma unroll
        for (int ii = 0; ii < 2; ii++) {
            int i = tid + ii * 256;          // 0..511 slots
            int ln = i & 31;
            int np = (i >> 5) & 3;
            int s  = i >> 7;                 // 0..3
            int tgg = ln & 3, gg = ln >> 2;
            int n0 = 16 * np + gg;
            int n1 = n0 + 8;
            unsigned* dst = &Wp[l * 2048 + i * 4];
            if (l == 0) {
                int r = 16 * tgg + 4 * s;    // slot0 rows r,r+1; slot1 rows r+2,r+3
                dst[0] = h2(__ldg(&W[r * 64 + n0]),       __ldg(&W[(r + 1) * 64 + n0]));
                dst[1] = h2(__ldg(&W[(r + 2) * 64 + n0]), __ldg(&W[(r + 3) * 64 + n0]));
                dst[2] = h2(__ldg(&W[r * 64 + n1]),       __ldg(&W[(r + 1) * 64 + n1]));
                dst[3] = h2(__ldg(&W[(r + 2) * 64 + n1]), __ldg(&W[(r + 3) * 64 + n1]));
            } else {
                int ra = 16 * s + 2 * tgg;       // slot0 rows
                int rb = ra + 8;                 // slot1 rows
                dst[0] = h2(__ldg(&W[ra * 64 + n0]),       __ldg(&W[(ra + 1) * 64 + n0]));
                dst[1] = h2(__ldg(&W[rb * 64 + n0]),       __ldg(&W[(rb + 1) * 64 + n0]));
                dst[2] = h2(__ldg(&W[ra * 64 + n1]),       __ldg(&W[(ra + 1) * 64 + n1]));
                dst[3] = h2(__ldg(&W[rb * 64 + n1]),       __ldg(&W[(rb + 1) * 64 + n1]));
            }
        }
    }
    __syncthreads();   // the only block barrier

    // ---- Per-warp coalesced ingress: own 16 rows of half2(X + agg) ----
    // Ts half layout: row r, word m (0..31) = phys cols (2m, 2m+1).
    #pragma unroll
    for (int i = 0; i < 8; i++) {
        int idx = i * 32 + lane;             // 0..255 float4 within warp tile
        int r  = warp * 16 + (idx >> 4);     // local row (warp-private)
        int c4 = idx & 15;
        int grow = row0 + r;
        uint2 st = make_uint2(0u, 0u);
        if (grow < N_NODES) {
            float4 a = agg4[(size_t)grow * 16 + c4];
            float4 x = __ldg(&X4[(size_t)grow * 16 + c4]);
            st.x = h2(a.x + x.x, a.y + x.y);
            st.y = h2(a.z + x.z, a.w + x.w);
        }
        *(uint2*)&Ts[r * TSW + c4 * 2] = st;
    }

    // Compiler barrier: agg loads above must materialize before the zeroing
    // stores below (same buffer!).
    asm volatile("" ::: "memory");

    // Re-zero own agg rows (fire-and-forget coalesced stores).
    {
        const float4 z4 = make_float4(0.f, 0.f, 0.f, 0.f);
        #pragma unroll
        for (int i = 0; i < 8; i++) {
            int idx = i * 32 + lane;
            int grow = row0 + warp * 16 + (idx >> 4);
            if (grow < N_NODES)
                agg4[(size_t)grow * 16 + (idx & 15)] = z4;
        }
    }
    __syncwarp();

    // ---- Pull A fragments: words [8tg, 8tg+8) of own two rows ----
    const int lr0 = warp * 16 + g;
    const int lr1 = lr0 + 8;
    unsigned w0[8], w1[8];           // [m] = phys cols (16tg+2m, 16tg+2m+1)
    *(uint4*)&w0[0] = *(const uint4*)&Ts[lr0 * TSW + 8 * tg];
    *(uint4*)&w0[4] = *(const uint4*)&Ts[lr0 * TSW + 8 * tg + 4];
    *(uint4*)&w1[0] = *(const uint4*)&Ts[lr1 * TSW + 8 * tg];
    *(uint4*)&w1[4] = *(const uint4*)&Ts[lr1 * TSW + 8 * tg + 4];

    // ================= Layer 1 =================
    float acc[8][4];
    #pragma unroll
    for (int nt = 0; nt < 8; nt++) {
        float blo = __ldg(&bh[nt * 8 + 2 * tg]);
        float bhi = __ldg(&bh[nt * 8 + 2 * tg + 1]);
        acc[nt][0] = blo; acc[nt][1] = bhi; acc[nt][2] = blo; acc[nt][3] = bhi;
    }
    #pragma unroll
    for (int s = 0; s < 4; s++) {
        unsigned A0 = w0[2 * s],     A1 = w1[2 * s];
        unsigned A2 = w0[2 * s + 1], A3 = w1[2 * s + 1];
        #pragma unroll
        for (int np = 0; np < 4; np++) {
            uint4 b = *(const uint4*)&Wp[((s * 4 + np) * 32 + lane) * 4];
            mma_f16(acc[2 * np],     A0, A1, A2, A3, b.x, b.y);
            mma_f16(acc[2 * np + 1], A0, A1, A2, A3, b.z, b.w);
        }
    }

    // ---- relu + pack: accumulators become layer-2 A fragments directly ----
    // step s: a0 <- acc[2s]{0,1} (row g), a1 <- acc[2s]{2,3} (row g+8),
    //         a2 <- acc[2s+1]{0,1},      a3 <- acc[2s+1]{2,3}
    unsigned ha0[4], ha1[4], ha2[4], ha3[4];
    #pragma unroll
    for (int s = 0; s < 4; s++) {
        ha0[s] = h2(fmaxf(acc[2 * s][0], 0.f),     fmaxf(acc[2 * s][1], 0.f));
        ha1[s] = h2(fmaxf(acc[2 * s][2], 0.f),     fmaxf(acc[2 * s][3], 0.f));
        ha2[s] = h2(fmaxf(acc[2 * s + 1][0], 0.f), fmaxf(acc[2 * s + 1][1], 0.f));
        ha3[s] = h2(fmaxf(acc[2 * s + 1][2], 0.f), fmaxf(acc[2 * s + 1][3], 0.f));
    }

    // ================= Layer 2 =================
    #pragma unroll
    for (int nt = 0; nt < 8; nt++) {
        float blo = __ldg(&bo[nt * 8 + 2 * tg]);
        float bhi = __ldg(&bo[nt * 8 + 2 * tg + 1]);
        acc[nt][0] = blo; acc[nt][1] = bhi; acc[nt][2] = blo; acc[nt][3] = bhi;
    }
    #pragma unroll
    for (int s = 0; s < 4; s++) {
        #pragma unroll
        for (int np = 0; np < 4; np++) {
            uint4 b = *(const uint4*)&Wp[2048 + ((s * 4 + np) * 32 + lane) * 4];
            mma_f16(acc[2 * np],     ha0[s], ha1[s], ha2[s], ha3[s], b.x, b.y);
            mma_f16(acc[2 * np + 1], ha0[s], ha1[s], ha2[s], ha3[s], b.z, b.w);
        }
    }

    // ---- Egress: relu -> own warp stripe as fp32 (warp-private) ----
    __syncwarp();
    #pragma unroll
    for (int nt = 0; nt < 8; nt++) {
        int c = nt * 8 + 2 * tg;
        *(uint2*)&Ts[lr0 * TSW + c] = make_uint2(
            __float_as_uint(fmaxf(acc[nt][0], 0.f)),
            __float_as_uint(fmaxf(acc[nt][1], 0.f)));
        *(uint2*)&Ts[lr1 * TSW + c] = make_uint2(
            __float_as_uint(fmaxf(acc[nt][2], 0.f)),
            __float_as_uint(fmaxf(acc[nt][3], 0.f)));
    }
    __syncwarp();

    // ---- Per-warp coalesced STG.128 of own 16 output rows ----
    #pragma unroll
    for (int i = 0; i < 8; i++) {
        int idx = i * 32 + lane;
        int r  = warp * 16 + (idx >> 4);
        int c4 = idx & 15;
        int grow = row0 + r;
        if (grow < N_NODES) {
            uint4 v = *(const uint4*)&Ts[r * TSW + c4 * 4];
            out4[(size_t)grow * 16 + c4] = make_float4(
                __uint_as_float(v.x), __uint_as_float(v.y),
                __uint_as_float(v.z), __uint_as_float(v.w));
        }
    }
}

// ---------------------------------------------------------------------------
// Inputs: 0=X, 1=ref_a, 2=ref_b, 3=v_map(unused), 4=v_count(unused),
//         5=W_hidden, 6=b_hidden, 7=W_out, 8=b_out
// ---------------------------------------------------------------------------
extern "C" void kernel_launch(void* const* d_in, const int* in_sizes, int n_in,
                              void* d_out, int out_size) {
    const float* X   = (const float*)d_in[0];
    const int* ref_a = (const int*)d_in[1];
    const int* ref_b = (const int*)d_in[2];
    const float* Wh  = (const float*)d_in[5];
    const float* bh  = (const float*)d_in[6];
    const float* Wo  = (const float*)d_in[7];
    const float* bo  = (const float*)d_in[8];
    float* out = (float*)d_out;

    float* agg;
    cudaGetSymbolAddress((void**)&agg, g_agg);

    // 1) edge scatter into zeroed agg (zero-invariant maintained by k_mlp)
    {
        long long total = (long long)N_EDGES * 16;
        int blocks = (int)((total + 255) / 256);
        k_scatter<<<blocks, 256>>>((const float4*)X, ref_a, ref_b);
    }

    // 2) FP16 register-fragment MLP (adds X, consumes agg, re-zeroes agg)
    {
        cudaFuncSetAttribute(k_mlp, cudaFuncAttributeMaxDynamicSharedMemorySize,
                             MLP_SMEM);
        int blocks = (N_NODES + 127) / 128;   // 782
        k_mlp<<<blocks, 256, MLP_SMEM>>>((float4*)agg, (const float4*)X,
                                         Wh, bh, Wo, bo, (float4*)out);
    }
}